// round 5
// baseline (speedup 1.0000x reference)
#include <cuda_runtime.h>
#include <stdint.h>

#define HH 721
#define WW 1440
#define NPTS (HH*WW)
#define NQ4  (NPTS/4)
#define BB 16
#define CC 4
#define DD 256
#define NV 12
#define PI_D 3.141592653589793
#define TWOPI_D (2.0*PI_D)

static __device__ float              g_vlat[NV];
static __device__ float              g_vlon[NV];
static __device__ unsigned long long g_v2g[NV];
static __device__ unsigned char      g_vmap[NPTS];
static __device__ float              g_hnA[BB*NV*DD];
static __device__ float              g_hnB[BB*NV*DD];
static __device__ float              g_nodes[BB*NV*CC];

__constant__ signed char c_vcode[NV][3] = {
    {-1,2,0},{1,2,0},{-1,-2,0},{1,-2,0},{0,-1,2},{0,1,2},
    {0,-1,-2},{0,1,-2},{2,0,-1},{2,0,1},{-2,0,-1},{-2,0,1}};
__constant__ int c_nbr[NV][5] = {
    {11,5,1,7,10},{0,5,7,9,8},{11,10,3,4,6},{9,4,2,6,8},
    {5,11,3,9,2},{0,11,1,9,4},{10,7,3,2,8},{0,1,10,6,8},
    {7,1,3,6,9},{1,5,3,4,8},{0,7,11,2,6},{0,5,10,2,4}};

// K0: vertex lat/lon in f32 (mirrors numpy f32 _VERTS + XLA asin/atan2)
__global__ void k_setup() {
    int v = threadIdx.x;
    if (v >= NV) return;
    float phi = (float)((1.0 + sqrt(5.0)) * 0.5);
    float c[3];
#pragma unroll
    for (int k = 0; k < 3; k++) {
        int cd = c_vcode[v][k];
        float m = (cd == 2 || cd == -2) ? phi : 1.0f;
        c[k] = (cd == 0) ? 0.0f : (cd < 0 ? -m : m);
    }
    float n2 = __fadd_rn(__fadd_rn(__fmul_rn(c[0],c[0]), __fmul_rn(c[1],c[1])), __fmul_rn(c[2],c[2]));
    float nrm = __fsqrt_rn(n2);
    float x = __fdiv_rn(c[0],nrm), y = __fdiv_rn(c[1],nrm), z = __fdiv_rn(c[2],nrm);
    float s = __fsqrt_rn(__fsub_rn(1.0f, __fmul_rn(z,z)));
    g_vlat[v] = __fmul_rn(2.0f, atan2f(z, __fadd_rn(1.0f, s)));
    g_vlon[v] = atan2f(y, x);
    g_v2g[v] = 0xFFFFFFFFFFFFFFFFULL;
}

// K1: nearest-vertex per output pixel + per-vertex nearest point. FP64 geometry (x64 semantics).
__global__ void __launch_bounds__(256) k_vmap() {
    __shared__ double svlat[NV], svlon[NV];
    __shared__ unsigned long long sm[NV];
    int t = threadIdx.x;
    if (t < NV) { svlat[t] = (double)g_vlat[t]; svlon[t] = (double)g_vlon[t]; sm[t] = ~0ULL; }
    __syncthreads();
    int o = blockIdx.x * 256 + t;
    if (o < NPTS) {
        int i = o / WW, j = o - i * WW;
        int p = j * HH + i;                 // reshape(lon,lat).T scramble
        int li = p / WW, lj = p - li * WW;
        double dla_s = __ddiv_rn(PI_D, 720.0);
        double dlo_s = __ddiv_rn(TWOPI_D, 1439.0);
        double lat = __dadd_rn(-(PI_D*0.5), __dmul_rn((double)li, dla_s));
        double lon = __dadd_rn(-PI_D,       __dmul_rn((double)lj, dlo_s));
        if (li == 360) lat = 1.0e-12;       // pin symmetry row to inferred positive side
        double best = 1.0e300; int bestv = 0;
#pragma unroll
        for (int v = 0; v < NV; v++) {
            double dla = __dsub_rn(lat, svlat[v]);
            double raw = __dadd_rn(__dsub_rn(lon, svlon[v]), PI_D);
            double r = raw;
            if (raw >= TWOPI_D)    r = __dsub_rn(raw, TWOPI_D);
            else if (raw < 0.0)    r = __dadd_rn(raw, TWOPI_D);
            double dlo = __dsub_rn(r, PI_D);
            double d2 = __dadd_rn(__dmul_rn(dla,dla), __dmul_rn(dlo,dlo));
            if (d2 < best) { best = d2; bestv = v; }
            unsigned long long pk =
                ((unsigned long long)__float_as_uint(__double2float_rn(d2)) << 32) | (unsigned)p;
            if (pk < sm[v]) atomicMin(&sm[v], pk);
        }
        g_vmap[o] = (unsigned char)bestv;
    }
    __syncthreads();
    if (t < NV) atomicMin(&g_v2g[t], sm[t]);
}

// K2: gather 12 points + input projection
__global__ void __launch_bounds__(256) k_inproj(const float* __restrict__ x,
                                                const float* __restrict__ Win,
                                                const float* __restrict__ bin) {
    int bx = blockIdx.x, b = bx / NV, v = bx - b * NV, d = threadIdx.x;
    unsigned p = (unsigned)(g_v2g[v] & 0xFFFFFFFFu);
    int pi = p / WW, pj = p - pi * WW;
    const float* xb = x + ((long)(b * CC) * HH + pi) * WW + pj;
    float acc = bin[d];
    acc = fmaf(__ldg(xb + 0L*HH*WW), Win[0*DD+d], acc);
    acc = fmaf(__ldg(xb + 1L*HH*WW), Win[1*DD+d], acc);
    acc = fmaf(__ldg(xb + 2L*HH*WW), Win[2*DD+d], acc);
    acc = fmaf(__ldg(xb + 3L*HH*WW), Win[3*DD+d], acc);
    g_hnA[bx * DD + d] = acc;
}

// K3: one GNN layer (ping-pong, 2 batches/block)
__global__ void __launch_bounds__(256) k_layer(const float* __restrict__ Wfull,
                                               const float* __restrict__ bl, int l, int dir) {
    const float* src = dir ? g_hnB : g_hnA;
    float*       dst = dir ? g_hnA : g_hnB;
    int v = blockIdx.x, b0 = blockIdx.y * 2, d = threadIdx.x;
    __shared__ float sagg[2][DD];
#pragma unroll
    for (int bb = 0; bb < 2; bb++) {
        const float* base = src + (b0 + bb) * NV * DD;
        float s = base[c_nbr[v][0]*DD + d];
        s = __fadd_rn(s, base[c_nbr[v][1]*DD + d]);
        s = __fadd_rn(s, base[c_nbr[v][2]*DD + d]);
        s = __fadd_rn(s, base[c_nbr[v][3]*DD + d]);
        s = __fadd_rn(s, base[c_nbr[v][4]*DD + d]);
        sagg[bb][d] = __fdiv_rn(s, 5.0f);
    }
    __syncthreads();
    const float* W = Wfull + l * DD * DD;
    float bias = bl[l * DD + d], a0 = bias, a1 = bias;
#pragma unroll 8
    for (int k = 0; k < DD; k++) {
        float w = W[k * DD + d];
        a0 = fmaf(sagg[0][k], w, a0);
        a1 = fmaf(sagg[1][k], w, a1);
    }
    dst[((b0+0)*NV+v)*DD+d] = src[((b0+0)*NV+v)*DD+d] + fmaxf(a0, 0.0f);
    dst[((b0+1)*NV+v)*DD+d] = src[((b0+1)*NV+v)*DD+d] + fmaxf(a1, 0.0f);
}

// K4: output projection
__global__ void __launch_bounds__(256) k_outproj(const float* __restrict__ Wout,
                                                 const float* __restrict__ bout) {
    int bv = blockIdx.x, d = threadIdx.x;
    __shared__ float red[DD * CC];
    float h = g_hnA[bv * DD + d];
#pragma unroll
    for (int c = 0; c < CC; c++) red[d * CC + c] = h * Wout[d * CC + c];
    __syncthreads();
    for (int s = 128; s > 0; s >>= 1) {
        if (d < s)
#pragma unroll
            for (int c = 0; c < CC; c++) red[d*CC+c] += red[(d+s)*CC+c];
        __syncthreads();
    }
    if (d < CC) g_nodes[bv * CC + d] = red[d] + bout[d];
}

// K5: output scatter (write-bound: uchar4 in, float4 out)
__global__ void __launch_bounds__(256) k_scatter(float* __restrict__ out) {
    int b = blockIdx.z, c = blockIdx.y;
    __shared__ float sval[NV];
    if (threadIdx.x < NV) sval[threadIdx.x] = g_nodes[(b * NV + threadIdx.x) * CC + c];
    __syncthreads();
    int q = blockIdx.x * 256 + threadIdx.x;
    if (q < NQ4) {
        uchar4 vm = reinterpret_cast<const uchar4*>(g_vmap)[q];
        float4 o;
        o.x = sval[vm.x]; o.y = sval[vm.y]; o.z = sval[vm.z]; o.w = sval[vm.w];
        reinterpret_cast<float4*>(out)[(long)(b * CC + c) * NQ4 + q] = o;
    }
}

extern "C" void kernel_launch(void* const* d_in, const int* in_sizes, int n_in,
                              void* d_out, int out_size) {
    const float* x        = (const float*)d_in[0];
    const float* W_in     = (const float*)d_in[2];
    const float* b_in     = (const float*)d_in[3];
    const float* W_layers = (const float*)d_in[4];
    const float* b_layers = (const float*)d_in[5];
    const float* W_out    = (const float*)d_in[6];
    const float* b_out    = (const float*)d_in[7];
    float* out = (float*)d_out;

    k_setup<<<1, 32>>>();
    k_vmap<<<(NPTS + 255) / 256, 256>>>();
    k_inproj<<<BB * NV, 256>>>(x, W_in, b_in);
    k_layer<<<dim3(NV, BB/2), 256>>>(W_layers, b_layers, 0, 0);
    k_layer<<<dim3(NV, BB/2), 256>>>(W_layers, b_layers, 1, 1);
    k_layer<<<dim3(NV, BB/2), 256>>>(W_layers, b_layers, 2, 0);
    k_layer<<<dim3(NV, BB/2), 256>>>(W_layers, b_layers, 3, 1);
    k_outproj<<<BB * NV, 256>>>(W_out, b_out);
    k_scatter<<<dim3((NQ4 + 255) / 256, CC, BB), 256>>>(out);
}

// round 7
// speedup vs baseline: 2.3671x; 2.3671x over previous
#include <cuda_runtime.h>
#include <stdint.h>

#define HH 721
#define WW 1440
#define NPTS (HH*WW)
#define NQ4  (NPTS/4)
#define BB 16
#define CC 4
#define DD 256
#define NV 12
#define PI_D 3.141592653589793
#define TWOPI_D (2.0*PI_D)

static __device__ double        g_dla2d[NV][HH];    // f64 (lat-vlat)^2 per (v,li)
static __device__ double        g_dlo2d[NV][WW];    // f64 (dlon)^2 per (v,lj)
static __device__ float         g_dla2f[NV][HH];    // f32 copies for fast path
static __device__ float         g_dlo2f[NV][WW];
static __device__ unsigned int  g_v2gi[NV];         // nearest grid point per vertex
static __device__ unsigned char g_vmap[NPTS];       // vertex id per OUTPUT pixel
static __device__ float         g_hnA[BB*NV*DD];
static __device__ float         g_hnB[BB*NV*DD];
static __device__ float         g_nodes[BB*NV*CC];

__constant__ signed char c_vcode[NV][3] = {
    {-1,2,0},{1,2,0},{-1,-2,0},{1,-2,0},{0,-1,2},{0,1,2},
    {0,-1,-2},{0,1,-2},{2,0,-1},{2,0,1},{-2,0,-1},{-2,0,1}};
__constant__ int c_nbr[NV][5] = {
    {11,5,1,7,10},{0,5,7,9,8},{11,10,3,4,6},{9,4,2,6,8},
    {5,11,3,9,2},{0,11,1,9,4},{10,7,3,2,8},{0,1,10,6,8},
    {7,1,3,6,9},{1,5,3,4,8},{0,7,11,2,6},{0,5,10,2,4}};

// ---- K0: vertex lat/lon (f32, as before) + separable f64 distance tables + v2g ----
__global__ void __launch_bounds__(1024) k_tab() {
    __shared__ double svlat[NV], svlon[NV];
    __shared__ int sli[NV], slj[NV];
    int t = threadIdx.x;

    if (t < NV) {
        float phi = (float)((1.0 + sqrt(5.0)) * 0.5);
        float c[3];
#pragma unroll
        for (int k = 0; k < 3; k++) {
            int cd = c_vcode[t][k];
            float m = (cd == 2 || cd == -2) ? phi : 1.0f;
            c[k] = (cd == 0) ? 0.0f : (cd < 0 ? -m : m);
        }
        float n2 = __fadd_rn(__fadd_rn(__fmul_rn(c[0],c[0]), __fmul_rn(c[1],c[1])),
                             __fmul_rn(c[2],c[2]));
        float nrm = __fsqrt_rn(n2);
        float x = __fdiv_rn(c[0],nrm), y = __fdiv_rn(c[1],nrm), z = __fdiv_rn(c[2],nrm);
        float s = __fsqrt_rn(__fsub_rn(1.0f, __fmul_rn(z,z)));
        svlat[t] = (double)__fmul_rn(2.0f, atan2f(z, __fadd_rn(1.0f, s)));  // XLA asin
        svlon[t] = (double)atan2f(y, x);
    }
    __syncthreads();

    // lat table (721 rows)
    if (t < HH) {
        double dla_s = __ddiv_rn(PI_D, 720.0);
        double lat = __dadd_rn(-(PI_D*0.5), __dmul_rn((double)t, dla_s));
        if (t == 360) lat = 1.0e-12;   // symmetry row pinned positive (validated R5)
#pragma unroll
        for (int v = 0; v < NV; v++) {
            double dla = __dsub_rn(lat, svlat[v]);
            double q = __dmul_rn(dla, dla);
            g_dla2d[v][t] = q;
            g_dla2f[v][t] = (float)q;
        }
    }
    // lon table (1440 cols)
    for (int lj = t; lj < WW; lj += 1024) {
        double dlo_s = __ddiv_rn(TWOPI_D, 1439.0);
        double lon = __dadd_rn(-PI_D, __dmul_rn((double)lj, dlo_s));
#pragma unroll
        for (int v = 0; v < NV; v++) {
            double raw = __dadd_rn(__dsub_rn(lon, svlon[v]), PI_D);
            double r = raw;
            if (raw >= TWOPI_D)   r = __dsub_rn(raw, TWOPI_D);
            else if (raw < 0.0)   r = __dadd_rn(raw, TWOPI_D);
            double dlo = __dsub_rn(r, PI_D);
            double q = __dmul_rn(dlo, dlo);
            g_dlo2d[v][lj] = q;
            g_dlo2f[v][lj] = (float)q;
        }
    }
    __syncthreads();

    // v2g: separable argmin (rounded sum is monotone => argmin splits; lex tie-break == first-p)
    int w = t / 32, lane = t % 32;
    if (w < 24) {
        int v = w % NV;
        bool lonp = (w >= NV);
        int n = lonp ? WW : HH;
        const double* tab = lonp ? g_dlo2d[v] : g_dla2d[v];
        double bv = 1.0e300; int bi = 0;
        for (int i = lane; i < n; i += 32) {
            double q = tab[i];
            if (q < bv) { bv = q; bi = i; }          // strided: indices increasing per lane
        }
#pragma unroll
        for (int off = 16; off > 0; off >>= 1) {
            double ov = __shfl_down_sync(0xFFFFFFFFu, bv, off);
            int    oi = __shfl_down_sync(0xFFFFFFFFu, bi, off);
            if (ov < bv || (ov == bv && oi < bi)) { bv = ov; bi = oi; }
        }
        if (lane == 0) { if (lonp) slj[v] = bi; else sli[v] = bi; }
    }
    __syncthreads();
    if (t < NV) g_v2gi[t] = (unsigned)(sli[t] * WW + slj[t]);
}

// ---- K1: per-pixel nearest vertex; f32 fast path + exact f64 fallback near boundaries ----
__global__ void __launch_bounds__(256) k_vmap() {
    __shared__ float sa[NV];
    __shared__ float sb[NV][256];
    int t = threadIdx.x;
    int li = blockIdx.y;
    int lj0 = blockIdx.x * 256;
    if (t < NV) sa[t] = g_dla2f[t][li];
#pragma unroll
    for (int v = 0; v < NV; v++) {
        int lj = lj0 + t;
        sb[v][t] = (lj < WW) ? g_dlo2f[v][lj] : 1.0e30f;
    }
    __syncthreads();

    int lj = lj0 + t;
    if (lj >= WW) return;
    float b1 = 1.0e30f, b2 = 1.0e30f; int bv = 0;
#pragma unroll
    for (int v = 0; v < NV; v++) {
        float s = sa[v] + sb[v][t];
        if (s < b1) { b2 = b1; b1 = s; bv = v; }
        else if (s < b2) { b2 = s; }
    }
    if (b2 - b1 < 1.0e-4f) {   // ambiguous in f32 -> replay exact f64 reference compare
        double best = 1.0e300; bv = 0;
#pragma unroll
        for (int v = 0; v < NV; v++) {
            double s = __dadd_rn(g_dla2d[v][li], g_dlo2d[v][lj]);
            if (s < best) { best = s; bv = v; }      // first-index tie-break
        }
    }
    int p = li * WW + lj;       // flat point index
    int j = p / HH;             // output col  (g2v = reshape(lon,lat).T scramble)
    int i = p - j * HH;         // output row
    g_vmap[i * WW + j] = (unsigned char)bv;
}

// ---- K2: gather 12 points + input projection ----
__global__ void __launch_bounds__(256) k_inproj(const float* __restrict__ x,
                                                const float* __restrict__ Win,
                                                const float* __restrict__ bin) {
    int bx = blockIdx.x, b = bx / NV, v = bx - b * NV, d = threadIdx.x;
    unsigned p = g_v2gi[v];
    int pi = p / WW, pj = p - pi * WW;
    const float* xb = x + ((long)(b * CC) * HH + pi) * WW + pj;
    float acc = bin[d];
    acc = fmaf(__ldg(xb + 0L*HH*WW), Win[0*DD+d], acc);
    acc = fmaf(__ldg(xb + 1L*HH*WW), Win[1*DD+d], acc);
    acc = fmaf(__ldg(xb + 2L*HH*WW), Win[2*DD+d], acc);
    acc = fmaf(__ldg(xb + 3L*HH*WW), Win[3*DD+d], acc);
    g_hnA[bx * DD + d] = acc;
}

// ---- K3: one GNN layer. One block per (v,b); 4-way ILP dot product. ----
__global__ void __launch_bounds__(256) k_layer(const float* __restrict__ Wfull,
                                               const float* __restrict__ bl, int l, int dir) {
    const float* src = dir ? g_hnB : g_hnA;
    float*       dst = dir ? g_hnA : g_hnB;
    int v = blockIdx.x, b = blockIdx.y, d = threadIdx.x;
    __shared__ float sagg[DD];
    const float* base = src + b * NV * DD;
    float s =  base[c_nbr[v][0]*DD + d];
    s = s +    base[c_nbr[v][1]*DD + d];
    s = s +    base[c_nbr[v][2]*DD + d];
    s = s +    base[c_nbr[v][3]*DD + d];
    s = s +    base[c_nbr[v][4]*DD + d];
    sagg[d] = s * 0.2f;          // deg == 5 exactly; tolerance allows recip-mul
    __syncthreads();

    const float* Wc = Wfull + l * DD * DD + d;
    float p0 = 0.f, p1 = 0.f, p2 = 0.f, p3 = 0.f;
#pragma unroll 8
    for (int k = 0; k < DD; k += 4) {
        p0 = fmaf(sagg[k+0], __ldg(Wc + (k+0)*DD), p0);
        p1 = fmaf(sagg[k+1], __ldg(Wc + (k+1)*DD), p1);
        p2 = fmaf(sagg[k+2], __ldg(Wc + (k+2)*DD), p2);
        p3 = fmaf(sagg[k+3], __ldg(Wc + (k+3)*DD), p3);
    }
    float a = ((p0 + p1) + (p2 + p3)) + bl[l * DD + d];
    int row = (b * NV + v) * DD + d;
    dst[row] = src[row] + fmaxf(a, 0.0f);
}

// ---- K4: output projection ----
__global__ void __launch_bounds__(256) k_outproj(const float* __restrict__ Wout,
                                                 const float* __restrict__ bout) {
    int bv = blockIdx.x, d = threadIdx.x;
    __shared__ float red[DD * CC];
    float h = g_hnA[bv * DD + d];
#pragma unroll
    for (int c = 0; c < CC; c++) red[d * CC + c] = h * Wout[d * CC + c];
    __syncthreads();
    for (int s = 128; s > 0; s >>= 1) {
        if (d < s)
#pragma unroll
            for (int c = 0; c < CC; c++) red[d*CC+c] += red[(d+s)*CC+c];
        __syncthreads();
    }
    if (d < CC) g_nodes[bv * CC + d] = red[d] + bout[d];
}

// ---- K5: output scatter (write-bound) ----
__global__ void __launch_bounds__(256) k_scatter(float* __restrict__ out) {
    int b = blockIdx.z, c = blockIdx.y;
    __shared__ float sval[NV];
    if (threadIdx.x < NV) sval[threadIdx.x] = g_nodes[(b * NV + threadIdx.x) * CC + c];
    __syncthreads();
    int q = blockIdx.x * 256 + threadIdx.x;
    if (q < NQ4) {
        uchar4 vm = reinterpret_cast<const uchar4*>(g_vmap)[q];
        float4 o;
        o.x = sval[vm.x]; o.y = sval[vm.y]; o.z = sval[vm.z]; o.w = sval[vm.w];
        reinterpret_cast<float4*>(out)[(long)(b * CC + c) * NQ4 + q] = o;
    }
}

extern "C" void kernel_launch(void* const* d_in, const int* in_sizes, int n_in,
                              void* d_out, int out_size) {
    const float* x        = (const float*)d_in[0];
    const float* W_in     = (const float*)d_in[2];
    const float* b_in     = (const float*)d_in[3];
    const float* W_layers = (const float*)d_in[4];
    const float* b_layers = (const float*)d_in[5];
    const float* W_out    = (const float*)d_in[6];
    const float* b_out    = (const float*)d_in[7];
    float* out = (float*)d_out;

    k_tab<<<1, 1024>>>();
    k_vmap<<<dim3((WW + 255) / 256, HH), 256>>>();
    k_inproj<<<BB * NV, 256>>>(x, W_in, b_in);
    k_layer<<<dim3(NV, BB), 256>>>(W_layers, b_layers, 0, 0);
    k_layer<<<dim3(NV, BB), 256>>>(W_layers, b_layers, 1, 1);
    k_layer<<<dim3(NV, BB), 256>>>(W_layers, b_layers, 2, 0);
    k_layer<<<dim3(NV, BB), 256>>>(W_layers, b_layers, 3, 1);
    k_outproj<<<BB * NV, 256>>>(W_out, b_out);
    k_scatter<<<dim3((NQ4 + 255) / 256, CC, BB), 256>>>(out);
}

// round 8
// speedup vs baseline: 3.1578x; 1.3341x over previous
#include <cuda_runtime.h>
#include <stdint.h>

#define HH 721
#define WW 1440
#define NPTS (HH*WW)
#define NQ4  (NPTS/4)
#define BB 16
#define CC 4
#define DD 256
#define NV 12
#define PI_D 3.141592653589793
#define TWOPI_D (2.0*PI_D)

static __device__ double        g_dla2d[NV][HH];
static __device__ double        g_dlo2d[NV][WW];
static __device__ float         g_dla2f[NV][HH];
static __device__ float         g_dlo2f[NV][WW];
static __device__ unsigned int  g_v2gi[NV];
static __device__ unsigned char g_vmap[NPTS];
static __device__ float         g_hnA[BB*NV*DD];
static __device__ float         g_hnB[BB*NV*DD];
static __device__ float         g_nodes[BB*NV*CC];
static __device__ float         g_WT[4*DD*DD];      // W_layers transposed: WT[l][d][k]

__constant__ signed char c_vcode[NV][3] = {
    {-1,2,0},{1,2,0},{-1,-2,0},{1,-2,0},{0,-1,2},{0,1,2},
    {0,-1,-2},{0,1,-2},{2,0,-1},{2,0,1},{-2,0,-1},{-2,0,1}};
__constant__ int c_nbr[NV][5] = {
    {11,5,1,7,10},{0,5,7,9,8},{11,10,3,4,6},{9,4,2,6,8},
    {5,11,3,9,2},{0,11,1,9,4},{10,7,3,2,8},{0,1,10,6,8},
    {7,1,3,6,9},{1,5,3,4,8},{0,7,11,2,6},{0,5,10,2,4}};

// ---- K0: per-vertex block — f64 distance tables + separable argmin (lex tie-break) ----
__global__ void __launch_bounds__(256) k_tab() {
    int v = blockIdx.x;
    int t = threadIdx.x;
    __shared__ double svlat, svlon;
    __shared__ double rv[8];
    __shared__ int    ri[8];
    __shared__ int    sbest[2];

    if (t == 0) {
        float phi = (float)((1.0 + sqrt(5.0)) * 0.5);
        float c[3];
#pragma unroll
        for (int k = 0; k < 3; k++) {
            int cd = c_vcode[v][k];
            float m = (cd == 2 || cd == -2) ? phi : 1.0f;
            c[k] = (cd == 0) ? 0.0f : (cd < 0 ? -m : m);
        }
        float n2 = __fadd_rn(__fadd_rn(__fmul_rn(c[0],c[0]), __fmul_rn(c[1],c[1])),
                             __fmul_rn(c[2],c[2]));
        float nrm = __fsqrt_rn(n2);
        float x = __fdiv_rn(c[0],nrm), y = __fdiv_rn(c[1],nrm), z = __fdiv_rn(c[2],nrm);
        float s = __fsqrt_rn(__fsub_rn(1.0f, __fmul_rn(z,z)));
        svlat = (double)__fmul_rn(2.0f, atan2f(z, __fadd_rn(1.0f, s)));   // XLA asin
        svlon = (double)atan2f(y, x);
    }
    __syncthreads();
    double vlat = svlat, vlon = svlon;

    // fill tables (strided), track per-thread argmin with increasing indices
    double bla = 1.0e300, blo = 1.0e300; int bia = 0, bio = 0;
    double dla_s = __ddiv_rn(PI_D, 720.0);
    double dlo_s = __ddiv_rn(TWOPI_D, 1439.0);
    for (int li = t; li < HH; li += 256) {
        double lat = __dadd_rn(-(PI_D*0.5), __dmul_rn((double)li, dla_s));
        if (li == 360) lat = 1.0e-12;            // symmetry row pinned positive (validated)
        double dla = __dsub_rn(lat, vlat);
        double q = __dmul_rn(dla, dla);
        g_dla2d[v][li] = q;
        g_dla2f[v][li] = (float)q;
        if (q < bla) { bla = q; bia = li; }
    }
    for (int lj = t; lj < WW; lj += 256) {
        double lon = __dadd_rn(-PI_D, __dmul_rn((double)lj, dlo_s));
        double raw = __dadd_rn(__dsub_rn(lon, vlon), PI_D);
        double r = raw;
        if (raw >= TWOPI_D)   r = __dsub_rn(raw, TWOPI_D);
        else if (raw < 0.0)   r = __dadd_rn(raw, TWOPI_D);
        double dlo = __dsub_rn(r, PI_D);
        double q = __dmul_rn(dlo, dlo);
        g_dlo2d[v][lj] = q;
        g_dlo2f[v][lj] = (float)q;
        if (q < blo) { blo = q; bio = lj; }
    }

    // two block-level (val,idx) argmin reductions, smaller-index tie-break
#pragma unroll
    for (int pass = 0; pass < 2; pass++) {
        double bv = pass ? blo : bla;
        int    bi = pass ? bio : bia;
#pragma unroll
        for (int off = 16; off > 0; off >>= 1) {
            double ov = __shfl_down_sync(0xFFFFFFFFu, bv, off);
            int    oi = __shfl_down_sync(0xFFFFFFFFu, bi, off);
            if (ov < bv || (ov == bv && oi < bi)) { bv = ov; bi = oi; }
        }
        if ((t & 31) == 0) { rv[t >> 5] = bv; ri[t >> 5] = bi; }
        __syncthreads();
        if (t < 8) {
            bv = rv[t]; bi = ri[t];
#pragma unroll
            for (int off = 4; off > 0; off >>= 1) {
                double ov = __shfl_down_sync(0xFFu, bv, off);
                int    oi = __shfl_down_sync(0xFFu, bi, off);
                if (ov < bv || (ov == bv && oi < bi)) { bv = ov; bi = oi; }
            }
            if (t == 0) sbest[pass] = bi;
        }
        __syncthreads();
    }
    if (t == 0) g_v2gi[v] = (unsigned)(sbest[0] * WW + sbest[1]);
}

// ---- K1: per-pixel nearest vertex; f32 fast path + exact f64 fallback near boundaries ----
__global__ void __launch_bounds__(256) k_vmap() {
    __shared__ float sa[NV];
    __shared__ float sb[NV][256];
    int t = threadIdx.x;
    int li = blockIdx.y;
    int lj0 = blockIdx.x * 256;
    if (t < NV) sa[t] = g_dla2f[t][li];
#pragma unroll
    for (int v = 0; v < NV; v++) {
        int lj = lj0 + t;
        sb[v][t] = (lj < WW) ? g_dlo2f[v][lj] : 1.0e30f;
    }
    __syncthreads();

    int lj = lj0 + t;
    if (lj >= WW) return;
    float b1 = 1.0e30f, b2 = 1.0e30f; int bv = 0;
#pragma unroll
    for (int v = 0; v < NV; v++) {
        float s = sa[v] + sb[v][t];
        if (s < b1) { b2 = b1; b1 = s; bv = v; }
        else if (s < b2) { b2 = s; }
    }
    if (b2 - b1 < 1.0e-4f) {   // ambiguous in f32 -> exact f64 reference compare
        double best = 1.0e300; bv = 0;
#pragma unroll
        for (int v = 0; v < NV; v++) {
            double s = __dadd_rn(g_dla2d[v][li], g_dlo2d[v][lj]);
            if (s < best) { best = s; bv = v; }
        }
    }
    int p = li * WW + lj;
    int j = p / HH;             // g2v = reshape(lon,lat).T scramble
    int i = p - j * HH;
    g_vmap[i * WW + j] = (unsigned char)bv;
}

// ---- K2: transpose W_layers -> g_WT[l][d][k] (32x32 smem tiles) ----
__global__ void k_wt(const float* __restrict__ W) {
    __shared__ float tile[32][33];
    int l = blockIdx.z;
    int k0 = blockIdx.x * 32, d0 = blockIdx.y * 32;
    const float* src = W + l * DD * DD;
    float* dst = g_WT + l * DD * DD;
#pragma unroll
    for (int r = threadIdx.y; r < 32; r += 8)
        tile[r][threadIdx.x] = src[(k0 + r) * DD + d0 + threadIdx.x];
    __syncthreads();
#pragma unroll
    for (int r = threadIdx.y; r < 32; r += 8)
        dst[(d0 + r) * DD + k0 + threadIdx.x] = tile[threadIdx.x][r];
}

// ---- K3: gather 12 points + input projection ----
__global__ void __launch_bounds__(256) k_inproj(const float* __restrict__ x,
                                                const float* __restrict__ Win,
                                                const float* __restrict__ bin) {
    int bx = blockIdx.x, b = bx / NV, v = bx - b * NV, d = threadIdx.x;
    unsigned p = g_v2gi[v];
    int pi = p / WW, pj = p - pi * WW;
    const float* xb = x + ((long)(b * CC) * HH + pi) * WW + pj;
    float acc = bin[d];
    acc = fmaf(__ldg(xb + 0L*HH*WW), Win[0*DD+d], acc);
    acc = fmaf(__ldg(xb + 1L*HH*WW), Win[1*DD+d], acc);
    acc = fmaf(__ldg(xb + 2L*HH*WW), Win[2*DD+d], acc);
    acc = fmaf(__ldg(xb + 3L*HH*WW), Win[3*DD+d], acc);
    g_hnA[bx * DD + d] = acc;
}

// ---- K4: one GNN layer. grid (NV, BB, 2), block 128. float4 dot rows from g_WT. ----
__global__ void __launch_bounds__(128) k_layer(const float* __restrict__ bl, int l, int dir) {
    const float* src = dir ? g_hnB : g_hnA;
    float*       dst = dir ? g_hnA : g_hnB;
    int v = blockIdx.x, b = blockIdx.y;
    int d = blockIdx.z * 128 + threadIdx.x;

    __shared__ float sagg[DD];
    const float* base = src + b * NV * DD;
#pragma unroll
    for (int e = threadIdx.x; e < DD; e += 128) {
        float s = base[c_nbr[v][0]*DD + e] + base[c_nbr[v][1]*DD + e]
                + base[c_nbr[v][2]*DD + e] + base[c_nbr[v][3]*DD + e]
                + base[c_nbr[v][4]*DD + e];
        sagg[e] = s * 0.2f;
    }
    __syncthreads();

    const float4* w4 = reinterpret_cast<const float4*>(g_WT + (l * DD + d) * DD);
    const float4* s4 = reinterpret_cast<const float4*>(sagg);
    float4 acc = make_float4(0.f, 0.f, 0.f, 0.f);
#pragma unroll 16
    for (int k = 0; k < DD/4; k++) {
        float4 w = __ldg(&w4[k]);
        float4 s = s4[k];
        acc.x = fmaf(s.x, w.x, acc.x);
        acc.y = fmaf(s.y, w.y, acc.y);
        acc.z = fmaf(s.z, w.z, acc.z);
        acc.w = fmaf(s.w, w.w, acc.w);
    }
    float a = ((acc.x + acc.y) + (acc.z + acc.w)) + bl[l * DD + d];
    int row = (b * NV + v) * DD + d;
    dst[row] = src[row] + fmaxf(a, 0.0f);
}

// ---- K5: output projection ----
__global__ void __launch_bounds__(256) k_outproj(const float* __restrict__ Wout,
                                                 const float* __restrict__ bout) {
    int bv = blockIdx.x, d = threadIdx.x;
    __shared__ float red[DD * CC];
    float h = g_hnA[bv * DD + d];
#pragma unroll
    for (int c = 0; c < CC; c++) red[d * CC + c] = h * Wout[d * CC + c];
    __syncthreads();
    for (int s = 128; s > 0; s >>= 1) {
        if (d < s)
#pragma unroll
            for (int c = 0; c < CC; c++) red[d*CC+c] += red[(d+s)*CC+c];
        __syncthreads();
    }
    if (d < CC) g_nodes[bv * CC + d] = red[d] + bout[d];
}

// ---- K6: output scatter (write-bound) ----
__global__ void __launch_bounds__(256) k_scatter(float* __restrict__ out) {
    int b = blockIdx.z, c = blockIdx.y;
    __shared__ float sval[NV];
    if (threadIdx.x < NV) sval[threadIdx.x] = g_nodes[(b * NV + threadIdx.x) * CC + c];
    __syncthreads();
    int q = blockIdx.x * 256 + threadIdx.x;
    if (q < NQ4) {
        uchar4 vm = reinterpret_cast<const uchar4*>(g_vmap)[q];
        float4 o;
        o.x = sval[vm.x]; o.y = sval[vm.y]; o.z = sval[vm.z]; o.w = sval[vm.w];
        reinterpret_cast<float4*>(out)[(long)(b * CC + c) * NQ4 + q] = o;
    }
}

extern "C" void kernel_launch(void* const* d_in, const int* in_sizes, int n_in,
                              void* d_out, int out_size) {
    const float* x        = (const float*)d_in[0];
    const float* W_in     = (const float*)d_in[2];
    const float* b_in     = (const float*)d_in[3];
    const float* W_layers = (const float*)d_in[4];
    const float* b_layers = (const float*)d_in[5];
    const float* W_out    = (const float*)d_in[6];
    const float* b_out    = (const float*)d_in[7];
    float* out = (float*)d_out;

    k_wt<<<dim3(8, 8, 4), dim3(32, 8)>>>(W_layers);
    k_tab<<<NV, 256>>>();
    k_vmap<<<dim3((WW + 255) / 256, HH), 256>>>();
    k_inproj<<<BB * NV, 256>>>(x, W_in, b_in);
    k_layer<<<dim3(NV, BB, 2), 128>>>(b_layers, 0, 0);
    k_layer<<<dim3(NV, BB, 2), 128>>>(b_layers, 1, 1);
    k_layer<<<dim3(NV, BB, 2), 128>>>(b_layers, 2, 0);
    k_layer<<<dim3(NV, BB, 2), 128>>>(b_layers, 3, 1);
    k_outproj<<<BB * NV, 256>>>(W_out, b_out);
    k_scatter<<<dim3((NQ4 + 255) / 256, CC, BB), 256>>>(out);
}